// round 8
// baseline (speedup 1.0000x reference)
#include <cuda_runtime.h>
#include <cuda.h>
#include <stdint.h>
#include <math.h>

#define B_ 8
#define T_ 2048
#define D_ 768
#define KC 32
#define NSTAGE 3
#define LDS_ 36                       // padded row stride (floats): conflict-free frags
#define TILE_FLOATS (128 * LDS_)      // 4608 floats per operand tile
#define SMEM_DYN (2 * NSTAGE * TILE_FLOATS * 4)  // 3 stages x (A + B) = 110592 B

// Scratch: scores->(in-place) weights; transposed tf32 X; converted row-major X.
__device__ float g_S[(size_t)B_ * T_ * T_];
__device__ float g_Xt[(size_t)B_ * D_ * T_];
__device__ float g_Xc[(size_t)B_ * T_ * D_];

__device__ __forceinline__ uint32_t f2tf32(float v) {
    uint32_t o;
    asm("cvt.rna.tf32.f32 %0, %1;" : "=r"(o) : "f"(v));
    return o;
}

__device__ __forceinline__ void mma_tf32(float& c0, float& c1, float& c2, float& c3,
                                         uint32_t a0, uint32_t a1, uint32_t a2, uint32_t a3,
                                         uint32_t b0, uint32_t b1) {
    asm volatile(
        "mma.sync.aligned.m16n8k8.row.col.f32.tf32.tf32.f32 "
        "{%0,%1,%2,%3}, {%4,%5,%6,%7}, {%8,%9}, {%0,%1,%2,%3};"
        : "+f"(c0), "+f"(c1), "+f"(c2), "+f"(c3)
        : "r"(a0), "r"(a1), "r"(a2), "r"(a3), "r"(b0), "r"(b1));
}

struct Frag { float c[2][8][4]; };

// ---------------------------------------------------------------------------
// cp.async producer: one 128x32 fp32 chunk of each operand into given stage.
// GMEM data is already tf32-rounded, so raw byte copies preserve numerics.
// ---------------------------------------------------------------------------
__device__ __forceinline__ void issue_chunk(const float* __restrict__ A, int lda,
                                            const float* __restrict__ Bp, int ldb,
                                            int k0, uint32_t sA, uint32_t sB) {
    int tid = threadIdx.x;
    int row = tid >> 3, f4 = tid & 7;
#pragma unroll
    for (int p = 0; p < 4; p++) {
        int r = row + p * 32;
        const float* ga = A + (size_t)r * lda + k0 + f4 * 4;
        const float* gb = Bp + (size_t)r * ldb + k0 + f4 * 4;
        uint32_t da = sA + (uint32_t)(r * LDS_ + f4 * 4) * 4u;
        uint32_t db = sB + (uint32_t)(r * LDS_ + f4 * 4) * 4u;
        asm volatile("cp.async.cg.shared.global [%0], [%1], 16;" :: "r"(da), "l"(ga));
        asm volatile("cp.async.cg.shared.global [%0], [%1], 16;" :: "r"(db), "l"(gb));
    }
    asm volatile("cp.async.commit_group;" ::: "memory");
}

// ---------------------------------------------------------------------------
// Fragment loaders (scalar LDS, conflict-free via LDS_=36 padding).
// ---------------------------------------------------------------------------
__device__ __forceinline__ void load_frag_a(const uint32_t* __restrict__ sA,
                                            int wr, int g, int tg, int kc,
                                            uint32_t a[2][4]) {
#pragma unroll
    for (int m = 0; m < 2; m++) {
        int r0 = wr + m * 16 + g;
        a[m][0] = sA[r0 * LDS_ + kc + tg];
        a[m][1] = sA[(r0 + 8) * LDS_ + kc + tg];
        a[m][2] = sA[r0 * LDS_ + kc + tg + 4];
        a[m][3] = sA[(r0 + 8) * LDS_ + kc + tg + 4];
    }
}

__device__ __forceinline__ void load_frag_b(const uint32_t* __restrict__ sB,
                                            int wc, int g, int tg, int kc,
                                            uint32_t b[8][2]) {
#pragma unroll
    for (int n = 0; n < 8; n++) {
        int cn = wc + n * 8 + g;
        b[n][0] = sB[cn * LDS_ + kc + tg];
        b[n][1] = sB[cn * LDS_ + kc + tg + 4];
    }
}

// ---------------------------------------------------------------------------
// MMA consumer for one staged chunk — register double-buffered over ks so
// shared loads of ks+1 issue before the MMAs of ks (LDS latency hidden).
// ---------------------------------------------------------------------------
__device__ __forceinline__ void compute_chunk(const uint32_t* __restrict__ sA,
                                              const uint32_t* __restrict__ sB,
                                              Frag& fr) {
    int tid = threadIdx.x, wid = tid >> 5, lane = tid & 31;
    int wr = (wid >> 1) * 32;
    int wc = (wid & 1) * 64;
    int g = lane >> 2, tg = lane & 3;

    uint32_t a[2][2][4];
    uint32_t b[2][8][2];
    load_frag_a(sA, wr, g, tg, 0, a[0]);
    load_frag_b(sB, wc, g, tg, 0, b[0]);

#pragma unroll
    for (int ks = 0; ks < 4; ks++) {
        int cur = ks & 1, nxt = cur ^ 1;
        if (ks < 3) {
            load_frag_a(sA, wr, g, tg, (ks + 1) * 8, a[nxt]);
            load_frag_b(sB, wc, g, tg, (ks + 1) * 8, b[nxt]);
        }
#pragma unroll
        for (int n = 0; n < 8; n++)
#pragma unroll
            for (int m = 0; m < 2; m++)
                mma_tf32(fr.c[m][n][0], fr.c[m][n][1], fr.c[m][n][2], fr.c[m][n][3],
                         a[cur][m][0], a[cur][m][1], a[cur][m][2], a[cur][m][3],
                         b[cur][n][0], b[cur][n][1]);
    }
}

// ---------------------------------------------------------------------------
// 3-stage pipelined GEMM mainloop: C(128x128) += A(128xK) * B(128xK)^T.
// ---------------------------------------------------------------------------
__device__ __forceinline__ void run_gemm(const float* __restrict__ A, int lda,
                                         const float* __restrict__ Bp, int ldb,
                                         int nchunks, uint32_t* sm, Frag& fr) {
#pragma unroll
    for (int m = 0; m < 2; m++)
#pragma unroll
        for (int n = 0; n < 8; n++)
#pragma unroll
            for (int q = 0; q < 4; q++) fr.c[m][n][q] = 0.f;

    uint32_t sbase = (uint32_t)__cvta_generic_to_shared(sm);
    uint32_t stA[NSTAGE], stB[NSTAGE];
    const uint32_t* cA[NSTAGE];
    const uint32_t* cB[NSTAGE];
#pragma unroll
    for (int s = 0; s < NSTAGE; s++) {
        stA[s] = sbase + (uint32_t)(2 * s) * TILE_FLOATS * 4u;
        stB[s] = sbase + (uint32_t)(2 * s + 1) * TILE_FLOATS * 4u;
        cA[s] = sm + (size_t)(2 * s) * TILE_FLOATS;
        cB[s] = sm + (size_t)(2 * s + 1) * TILE_FLOATS;
    }

    issue_chunk(A, lda, Bp, ldb, 0, stA[0], stB[0]);
    if (nchunks > 1) issue_chunk(A, lda, Bp, ldb, KC, stA[1], stB[1]);

    int s = 0;
    for (int c = 0; c < nchunks; c++) {
        if (c + 1 < nchunks)
            asm volatile("cp.async.wait_group 1;" ::: "memory");
        else
            asm volatile("cp.async.wait_group 0;" ::: "memory");
        __syncthreads();
        if (c + 2 < nchunks) {
            int ns = s + 2; if (ns >= NSTAGE) ns -= NSTAGE;
            issue_chunk(A, lda, Bp, ldb, (c + 2) * KC, stA[ns], stB[ns]);
        }
        compute_chunk(cA[s], cB[s], fr);
        if (++s == NSTAGE) s = 0;
    }
}

// ---------------------------------------------------------------------------
// Kernel 1: S[b,i,j] = Xc[b,i,:].Xc[b,j,:] / sqrt(D)  (lower-triangle tiles)
// ---------------------------------------------------------------------------
__global__ void __launch_bounds__(256, 2) qk_mma_kernel() {
    int b = blockIdx.z;
    int i0 = blockIdx.y * 128;
    int j0 = blockIdx.x * 128;
    if (j0 > i0) return;

    extern __shared__ uint32_t sm[];
    const float* A = g_Xc + (size_t)b * T_ * D_ + (size_t)i0 * D_;
    const float* Bp = g_Xc + (size_t)b * T_ * D_ + (size_t)j0 * D_;

    Frag fr;
    run_gemm(A, D_, Bp, D_, D_ / KC, sm, fr);

    int tid = threadIdx.x, wid = tid >> 5, lane = tid & 31;
    int wr = (wid >> 1) * 32, wc = (wid & 1) * 64;
    int g = lane >> 2, tg = lane & 3;
    const float scl = 0.036084391824351615f;  // 1/sqrt(768)
    float* C = g_S + (size_t)b * T_ * T_;
#pragma unroll
    for (int m = 0; m < 2; m++) {
        int r0 = i0 + wr + m * 16 + g;
#pragma unroll
        for (int n = 0; n < 8; n++) {
            int cc = j0 + wc + n * 8 + tg * 2;
            float2 v0 = make_float2(fr.c[m][n][0] * scl, fr.c[m][n][1] * scl);
            float2 v1 = make_float2(fr.c[m][n][2] * scl, fr.c[m][n][3] * scl);
            *(float2*)(C + (size_t)r0 * T_ + cc) = v0;
            *(float2*)(C + (size_t)(r0 + 8) * T_ + cc) = v1;
        }
    }
}

// ---------------------------------------------------------------------------
// Kernel 2: in-place causal softmax + post-softmax sit_mask zeroing.
// Weights are tf32-rounded at the store so pv can cp.async raw bytes.
// ---------------------------------------------------------------------------
__global__ __launch_bounds__(256) void softmax_kernel(const float* __restrict__ mask) {
    int row = blockIdx.x;
    int b = row >> 11;
    int i = row & (T_ - 1);
    float* srow = g_S + (size_t)b * T_ * T_ + (size_t)i * T_;
    const float* mrow = mask + (size_t)b * T_;
    int tid = threadIdx.x;

    __shared__ float sh[T_];
    __shared__ float red[8];

    if (mrow[i] == 0.0f) {
        float4 z = make_float4(0.f, 0.f, 0.f, 0.f);
        for (int j4 = tid; j4 < T_ / 4; j4 += 256) ((float4*)srow)[j4] = z;
        return;
    }

    int n = i + 1;
    float lm = -3.4e38f;
    for (int j = tid; j < n; j += 256) { float v = srow[j]; sh[j] = v; lm = fmaxf(lm, v); }
#pragma unroll
    for (int o = 16; o > 0; o >>= 1) lm = fmaxf(lm, __shfl_xor_sync(0xffffffffu, lm, o));
    if ((tid & 31) == 0) red[tid >> 5] = lm;
    __syncthreads();
    float m = red[0];
#pragma unroll
    for (int k = 1; k < 8; k++) m = fmaxf(m, red[k]);
    __syncthreads();

    float ls = 0.f;
    for (int j = tid; j < n; j += 256) ls += __expf(sh[j] - m);
#pragma unroll
    for (int o = 16; o > 0; o >>= 1) ls += __shfl_xor_sync(0xffffffffu, ls, o);
    if ((tid & 31) == 0) red[tid >> 5] = ls;
    __syncthreads();
    float l = red[0];
#pragma unroll
    for (int k = 1; k < 8; k++) l += red[k];
    float inv = 1.0f / l;

    for (int j = tid; j < T_; j += 256) {
        float w = 0.f;
        if (j < n && mrow[j] != 0.f) w = __expf(sh[j] - m) * inv;
        srow[j] = __uint_as_float(f2tf32(w));
    }
}

// ---------------------------------------------------------------------------
// Kernel 2.5: Xt[b,d,j] = tf32(X[b,j,d]); Xc[b,j,d] = tf32(X[b,j,d]);
//             out[b,j,D+d] = X[b,j,d]  (concat half, unconverted)
// ---------------------------------------------------------------------------
__global__ __launch_bounds__(256) void transpose_concat_kernel(const float* __restrict__ X,
                                                               float* __restrict__ out) {
    __shared__ float t[32][33];
    int b = blockIdx.z, j0 = blockIdx.x * 32, d0 = blockIdx.y * 32;
    int tx = threadIdx.x, ty = threadIdx.y;
    const float* Xb = X + (size_t)b * T_ * D_;
    float* Xc = g_Xc + (size_t)b * T_ * D_;
#pragma unroll
    for (int r = 0; r < 32; r += 8) {
        float v = Xb[(size_t)(j0 + ty + r) * D_ + d0 + tx];
        float vt = __uint_as_float(f2tf32(v));
        t[ty + r][tx] = vt;
        out[((size_t)b * T_ + j0 + ty + r) * (2 * D_) + D_ + d0 + tx] = v;
        Xc[(size_t)(j0 + ty + r) * D_ + d0 + tx] = vt;
    }
    __syncthreads();
    float* Xt = g_Xt + (size_t)b * D_ * T_;
#pragma unroll
    for (int r = 0; r < 32; r += 8)
        Xt[(size_t)(d0 + ty + r) * T_ + j0 + tx] = t[tx][ty + r];
}

// ---------------------------------------------------------------------------
// Kernel 3: out[b,i,d] = sum_j W[b,i,j]*Xt[b,d,j]  (K truncated at i0+128).
// i-tiles mapped in DESCENDING K order so long-K CTAs launch first (wave LB).
// ---------------------------------------------------------------------------
__global__ void __launch_bounds__(256, 2) pv_mma_kernel(float* __restrict__ out) {
    int b = blockIdx.z;
    int i0 = (gridDim.y - 1 - blockIdx.y) * 128;   // big K first
    int d0 = blockIdx.x * 128;

    extern __shared__ uint32_t sm[];
    const float* A = g_S + (size_t)b * T_ * T_ + (size_t)i0 * T_;
    const float* Bp = g_Xt + (size_t)b * D_ * T_ + (size_t)d0 * T_;

    Frag fr;
    run_gemm(A, T_, Bp, T_, (i0 + 128) / KC, sm, fr);

    int tid = threadIdx.x, wid = tid >> 5, lane = tid & 31;
    int wr = (wid >> 1) * 32, wc = (wid & 1) * 64;
    int g = lane >> 2, tg = lane & 3;
#pragma unroll
    for (int m = 0; m < 2; m++) {
        int r0 = i0 + wr + m * 16 + g;
#pragma unroll
        for (int n = 0; n < 8; n++) {
            int cc = d0 + wc + n * 8 + tg * 2;
            float2 v0 = make_float2(fr.c[m][n][0], fr.c[m][n][1]);
            float2 v1 = make_float2(fr.c[m][n][2], fr.c[m][n][3]);
            *(float2*)(out + ((size_t)b * T_ + r0) * (2 * D_) + cc) = v0;
            *(float2*)(out + ((size_t)b * T_ + r0 + 8) * (2 * D_) + cc) = v1;
        }
    }
}

extern "C" void kernel_launch(void* const* d_in, const int* in_sizes, int n_in,
                              void* d_out, int out_size) {
    const float* X = (const float*)d_in[0];
    const float* mask = (const float*)d_in[1];
    // d_in[2] (proposition_matrix) is unused by the reference computation.
    float* out = (float*)d_out;

    cudaFuncSetAttribute(qk_mma_kernel, cudaFuncAttributeMaxDynamicSharedMemorySize, SMEM_DYN);
    cudaFuncSetAttribute(pv_mma_kernel, cudaFuncAttributeMaxDynamicSharedMemorySize, SMEM_DYN);

    dim3 gt(T_ / 32, D_ / 32, B_);
    transpose_concat_kernel<<<gt, dim3(32, 8)>>>(X, out);

    dim3 g1(T_ / 128, T_ / 128, B_);
    qk_mma_kernel<<<g1, 256, SMEM_DYN>>>();

    softmax_kernel<<<B_ * T_, 256>>>(mask);

    dim3 g3(D_ / 128, T_ / 128, B_);
    pv_mma_kernel<<<g3, 256, SMEM_DYN>>>(out);
}

// round 9
// speedup vs baseline: 1.3119x; 1.3119x over previous
#include <cuda_runtime.h>
#include <cuda.h>
#include <stdint.h>
#include <math.h>

#define B_ 8
#define T_ 2048
#define D_ 768
#define KC 32
#define LDS_ 36                       // padded row stride (floats): conflict-free frags
#define TILE_FLOATS (128 * LDS_)      // 4608 floats per operand tile
#define SMEM_DYN (4 * TILE_FLOATS * 4)  // 2 stages x (A + B) = 73728 B

// Scratch: scores->(in-place) weights; transposed tf32 X; converted row-major X.
__device__ float g_S[(size_t)B_ * T_ * T_];
__device__ float g_Xt[(size_t)B_ * D_ * T_];
__device__ float g_Xc[(size_t)B_ * T_ * D_];

__device__ __forceinline__ uint32_t f2tf32(float v) {
    uint32_t o;
    asm("cvt.rna.tf32.f32 %0, %1;" : "=r"(o) : "f"(v));
    return o;
}

__device__ __forceinline__ void mma_tf32(float& c0, float& c1, float& c2, float& c3,
                                         uint32_t a0, uint32_t a1, uint32_t a2, uint32_t a3,
                                         uint32_t b0, uint32_t b1) {
    asm volatile(
        "mma.sync.aligned.m16n8k8.row.col.f32.tf32.tf32.f32 "
        "{%0,%1,%2,%3}, {%4,%5,%6,%7}, {%8,%9}, {%0,%1,%2,%3};"
        : "+f"(c0), "+f"(c1), "+f"(c2), "+f"(c3)
        : "r"(a0), "r"(a1), "r"(a2), "r"(a3), "r"(b0), "r"(b1));
}

__device__ __forceinline__ void ldsm_x4(uint32_t& r0, uint32_t& r1, uint32_t& r2,
                                        uint32_t& r3, uint32_t addr) {
    asm volatile("ldmatrix.sync.aligned.m8n8.x4.shared.b16 {%0,%1,%2,%3}, [%4];"
                 : "=r"(r0), "=r"(r1), "=r"(r2), "=r"(r3) : "r"(addr));
}

struct Frag { float c[2][8][4]; };

// ---------------------------------------------------------------------------
// cp.async producer: one 128x32 fp32 chunk of each operand into given stage.
// GMEM data is already tf32-rounded, so raw byte copies preserve numerics.
// ---------------------------------------------------------------------------
__device__ __forceinline__ void issue_chunk(const float* __restrict__ A, int lda,
                                            const float* __restrict__ Bp, int ldb,
                                            int k0, uint32_t sA, uint32_t sB) {
    int tid = threadIdx.x;
    int row = tid >> 3, f4 = tid & 7;
#pragma unroll
    for (int p = 0; p < 4; p++) {
        int r = row + p * 32;
        const float* ga = A + (size_t)r * lda + k0 + f4 * 4;
        const float* gb = Bp + (size_t)r * ldb + k0 + f4 * 4;
        uint32_t da = sA + (uint32_t)(r * LDS_ + f4 * 4) * 4u;
        uint32_t db = sB + (uint32_t)(r * LDS_ + f4 * 4) * 4u;
        asm volatile("cp.async.cg.shared.global [%0], [%1], 16;" :: "r"(da), "l"(ga));
        asm volatile("cp.async.cg.shared.global [%0], [%1], 16;" :: "r"(db), "l"(gb));
    }
    asm volatile("cp.async.commit_group;" ::: "memory");
}

// ---------------------------------------------------------------------------
// MMA consumer for one staged chunk — ldmatrix.x4 fragment loads.
// Per ks: 2 LDSM (A, m=0/1) + 4 LDSM (B, 4 n-pairs) feeding 16 MMAs.
// ---------------------------------------------------------------------------
__device__ __forceinline__ void compute_chunk(uint32_t sA, uint32_t sB, Frag& fr) {
    int tid = threadIdx.x, wid = tid >> 5, lane = tid & 31;
    int wr = (wid >> 1) * 32;
    int wc = (wid & 1) * 64;

    // A addresses: matrix q = L>>3; rows wr + (L&7) + (q&1)*8 (+m*16), k-off (q>>1)*4
    uint32_t arow = (uint32_t)(wr + (lane & 7) + ((lane >> 3) & 1) * 8);
    uint32_t akof = (uint32_t)((lane >> 4) & 1) * 4u;
    uint32_t aAddr0 = sA + (arow * LDS_ + akof) * 4u;
    uint32_t aAddr1 = sA + ((arow + 16) * LDS_ + akof) * 4u;

    // B addresses: pair p covers n-frags 2p,2p+1; rows wc + p*16 + (q>>1)*8 + (L&7),
    // k-off (q&1)*4
    uint32_t brow = (uint32_t)(wc + ((lane >> 4) & 1) * 8 + (lane & 7));
    uint32_t bkof = (uint32_t)((lane >> 3) & 1) * 4u;
    uint32_t bAddr0 = sB + ((brow + 0) * LDS_ + bkof) * 4u;
    uint32_t bAddr1 = sB + ((brow + 16) * LDS_ + bkof) * 4u;
    uint32_t bAddr2 = sB + ((brow + 32) * LDS_ + bkof) * 4u;
    uint32_t bAddr3 = sB + ((brow + 48) * LDS_ + bkof) * 4u;

#pragma unroll
    for (int ks = 0; ks < 4; ks++) {
        uint32_t kb = (uint32_t)ks * 32u;   // 8 floats = 32 bytes per k-step
        uint32_t a[2][4];
        uint32_t bb[16];
        ldsm_x4(a[0][0], a[0][1], a[0][2], a[0][3], aAddr0 + kb);
        ldsm_x4(a[1][0], a[1][1], a[1][2], a[1][3], aAddr1 + kb);
        ldsm_x4(bb[0],  bb[1],  bb[2],  bb[3],  bAddr0 + kb);
        ldsm_x4(bb[4],  bb[5],  bb[6],  bb[7],  bAddr1 + kb);
        ldsm_x4(bb[8],  bb[9],  bb[10], bb[11], bAddr2 + kb);
        ldsm_x4(bb[12], bb[13], bb[14], bb[15], bAddr3 + kb);
#pragma unroll
        for (int n = 0; n < 8; n++) {
            uint32_t b0 = bb[(n >> 1) * 4 + (n & 1) * 2];
            uint32_t b1 = bb[(n >> 1) * 4 + (n & 1) * 2 + 1];
#pragma unroll
            for (int m = 0; m < 2; m++)
                mma_tf32(fr.c[m][n][0], fr.c[m][n][1], fr.c[m][n][2], fr.c[m][n][3],
                         a[m][0], a[m][1], a[m][2], a[m][3], b0, b1);
        }
    }
}

// ---------------------------------------------------------------------------
// Double-buffered GEMM mainloop (R6 structure): C(128x128) += A(128xK)*B(128xK)^T.
// ---------------------------------------------------------------------------
__device__ __forceinline__ void run_gemm(const float* __restrict__ A, int lda,
                                         const float* __restrict__ Bp, int ldb,
                                         int nchunks, uint32_t* sm, Frag& fr) {
#pragma unroll
    for (int m = 0; m < 2; m++)
#pragma unroll
        for (int n = 0; n < 8; n++)
#pragma unroll
            for (int q = 0; q < 4; q++) fr.c[m][n][q] = 0.f;

    uint32_t sbase = (uint32_t)__cvta_generic_to_shared(sm);
    uint32_t stA[2] = { sbase, sbase + 2u * TILE_FLOATS * 4u };
    uint32_t stB[2] = { sbase + TILE_FLOATS * 4u, sbase + 3u * TILE_FLOATS * 4u };

    issue_chunk(A, lda, Bp, ldb, 0, stA[0], stB[0]);
    for (int c = 0; c < nchunks; c++) {
        if (c + 1 < nchunks) {
            issue_chunk(A, lda, Bp, ldb, (c + 1) * KC, stA[(c + 1) & 1], stB[(c + 1) & 1]);
            asm volatile("cp.async.wait_group 1;" ::: "memory");
        } else {
            asm volatile("cp.async.wait_group 0;" ::: "memory");
        }
        __syncthreads();
        compute_chunk(stA[c & 1], stB[c & 1], fr);
        __syncthreads();
    }
}

// ---------------------------------------------------------------------------
// Kernel 1: S[b,i,j] = Xc[b,i,:].Xc[b,j,:] / sqrt(D)  (lower-triangle tiles)
// ---------------------------------------------------------------------------
__global__ void __launch_bounds__(256, 2) qk_mma_kernel() {
    int b = blockIdx.z;
    int i0 = blockIdx.y * 128;
    int j0 = blockIdx.x * 128;
    if (j0 > i0) return;

    extern __shared__ uint32_t sm[];
    const float* A = g_Xc + (size_t)b * T_ * D_ + (size_t)i0 * D_;
    const float* Bp = g_Xc + (size_t)b * T_ * D_ + (size_t)j0 * D_;

    Frag fr;
    run_gemm(A, D_, Bp, D_, D_ / KC, sm, fr);

    int tid = threadIdx.x, wid = tid >> 5, lane = tid & 31;
    int wr = (wid >> 1) * 32, wc = (wid & 1) * 64;
    int g = lane >> 2, tg = lane & 3;
    const float scl = 0.036084391824351615f;  // 1/sqrt(768)
    float* C = g_S + (size_t)b * T_ * T_;
#pragma unroll
    for (int m = 0; m < 2; m++) {
        int r0 = i0 + wr + m * 16 + g;
#pragma unroll
        for (int n = 0; n < 8; n++) {
            int cc = j0 + wc + n * 8 + tg * 2;
            float2 v0 = make_float2(fr.c[m][n][0] * scl, fr.c[m][n][1] * scl);
            float2 v1 = make_float2(fr.c[m][n][2] * scl, fr.c[m][n][3] * scl);
            *(float2*)(C + (size_t)r0 * T_ + cc) = v0;
            *(float2*)(C + (size_t)(r0 + 8) * T_ + cc) = v1;
        }
    }
}

// ---------------------------------------------------------------------------
// Kernel 2: in-place causal softmax + post-softmax sit_mask zeroing.
// Weights are tf32-rounded at the store so pv can cp.async raw bytes.
// ---------------------------------------------------------------------------
__global__ __launch_bounds__(256) void softmax_kernel(const float* __restrict__ mask) {
    int row = blockIdx.x;
    int b = row >> 11;
    int i = row & (T_ - 1);
    float* srow = g_S + (size_t)b * T_ * T_ + (size_t)i * T_;
    const float* mrow = mask + (size_t)b * T_;
    int tid = threadIdx.x;

    __shared__ float sh[T_];
    __shared__ float red[8];

    if (mrow[i] == 0.0f) {
        float4 z = make_float4(0.f, 0.f, 0.f, 0.f);
        for (int j4 = tid; j4 < T_ / 4; j4 += 256) ((float4*)srow)[j4] = z;
        return;
    }

    int n = i + 1;
    float lm = -3.4e38f;
    for (int j = tid; j < n; j += 256) { float v = srow[j]; sh[j] = v; lm = fmaxf(lm, v); }
#pragma unroll
    for (int o = 16; o > 0; o >>= 1) lm = fmaxf(lm, __shfl_xor_sync(0xffffffffu, lm, o));
    if ((tid & 31) == 0) red[tid >> 5] = lm;
    __syncthreads();
    float m = red[0];
#pragma unroll
    for (int k = 1; k < 8; k++) m = fmaxf(m, red[k]);
    __syncthreads();

    float ls = 0.f;
    for (int j = tid; j < n; j += 256) ls += __expf(sh[j] - m);
#pragma unroll
    for (int o = 16; o > 0; o >>= 1) ls += __shfl_xor_sync(0xffffffffu, ls, o);
    if ((tid & 31) == 0) red[tid >> 5] = ls;
    __syncthreads();
    float l = red[0];
#pragma unroll
    for (int k = 1; k < 8; k++) l += red[k];
    float inv = 1.0f / l;

    for (int j = tid; j < T_; j += 256) {
        float w = 0.f;
        if (j < n && mrow[j] != 0.f) w = __expf(sh[j] - m) * inv;
        srow[j] = __uint_as_float(f2tf32(w));
    }
}

// ---------------------------------------------------------------------------
// Kernel 2.5: Xt[b,d,j] = tf32(X[b,j,d]); Xc[b,j,d] = tf32(X[b,j,d]);
//             out[b,j,D+d] = X[b,j,d]  (concat half, unconverted)
// ---------------------------------------------------------------------------
__global__ __launch_bounds__(256) void transpose_concat_kernel(const float* __restrict__ X,
                                                               float* __restrict__ out) {
    __shared__ float t[32][33];
    int b = blockIdx.z, j0 = blockIdx.x * 32, d0 = blockIdx.y * 32;
    int tx = threadIdx.x, ty = threadIdx.y;
    const float* Xb = X + (size_t)b * T_ * D_;
    float* Xc = g_Xc + (size_t)b * T_ * D_;
#pragma unroll
    for (int r = 0; r < 32; r += 8) {
        float v = Xb[(size_t)(j0 + ty + r) * D_ + d0 + tx];
        float vt = __uint_as_float(f2tf32(v));
        t[ty + r][tx] = vt;
        out[((size_t)b * T_ + j0 + ty + r) * (2 * D_) + D_ + d0 + tx] = v;
        Xc[(size_t)(j0 + ty + r) * D_ + d0 + tx] = vt;
    }
    __syncthreads();
    float* Xt = g_Xt + (size_t)b * D_ * T_;
#pragma unroll
    for (int r = 0; r < 32; r += 8)
        Xt[(size_t)(d0 + ty + r) * T_ + j0 + tx] = t[tx][ty + r];
}

// ---------------------------------------------------------------------------
// Kernel 3: out[b,i,d] = sum_j W[b,i,j]*Xt[b,d,j]  (K truncated at i0+128).
// i-tiles mapped in DESCENDING K order so long-K CTAs launch first (wave LB).
// ---------------------------------------------------------------------------
__global__ void __launch_bounds__(256, 2) pv_mma_kernel(float* __restrict__ out) {
    int b = blockIdx.z;
    int i0 = (gridDim.y - 1 - blockIdx.y) * 128;   // big K first
    int d0 = blockIdx.x * 128;

    extern __shared__ uint32_t sm[];
    const float* A = g_S + (size_t)b * T_ * T_ + (size_t)i0 * T_;
    const float* Bp = g_Xt + (size_t)b * D_ * T_ + (size_t)d0 * T_;

    Frag fr;
    run_gemm(A, T_, Bp, T_, (i0 + 128) / KC, sm, fr);

    int tid = threadIdx.x, wid = tid >> 5, lane = tid & 31;
    int wr = (wid >> 1) * 32, wc = (wid & 1) * 64;
    int g = lane >> 2, tg = lane & 3;
#pragma unroll
    for (int m = 0; m < 2; m++) {
        int r0 = i0 + wr + m * 16 + g;
#pragma unroll
        for (int n = 0; n < 8; n++) {
            int cc = d0 + wc + n * 8 + tg * 2;
            float2 v0 = make_float2(fr.c[m][n][0], fr.c[m][n][1]);
            float2 v1 = make_float2(fr.c[m][n][2], fr.c[m][n][3]);
            *(float2*)(out + ((size_t)b * T_ + r0) * (2 * D_) + cc) = v0;
            *(float2*)(out + ((size_t)b * T_ + r0 + 8) * (2 * D_) + cc) = v1;
        }
    }
}

extern "C" void kernel_launch(void* const* d_in, const int* in_sizes, int n_in,
                              void* d_out, int out_size) {
    const float* X = (const float*)d_in[0];
    const float* mask = (const float*)d_in[1];
    // d_in[2] (proposition_matrix) is unused by the reference computation.
    float* out = (float*)d_out;

    cudaFuncSetAttribute(qk_mma_kernel, cudaFuncAttributeMaxDynamicSharedMemorySize, SMEM_DYN);
    cudaFuncSetAttribute(pv_mma_kernel, cudaFuncAttributeMaxDynamicSharedMemorySize, SMEM_DYN);

    dim3 gt(T_ / 32, D_ / 32, B_);
    transpose_concat_kernel<<<gt, dim3(32, 8)>>>(X, out);

    dim3 g1(T_ / 128, T_ / 128, B_);
    qk_mma_kernel<<<g1, 256, SMEM_DYN>>>();

    softmax_kernel<<<B_ * T_, 256>>>(mask);

    dim3 g3(D_ / 128, T_ / 128, B_);
    pv_mma_kernel<<<g3, 256, SMEM_DYN>>>(out);
}

// round 10
// speedup vs baseline: 1.3516x; 1.0302x over previous
#include <cuda_runtime.h>
#include <cuda.h>
#include <stdint.h>
#include <math.h>

#define B_ 8
#define T_ 2048
#define D_ 768
#define KC 32
#define NSTAGE 3
#define LDS_ 36                       // padded row stride (floats): conflict-free frags
#define TILE_FLOATS (128 * LDS_)      // 4608 floats per operand tile
#define SMEM_DYN (2 * NSTAGE * TILE_FLOATS * 4)  // 3 stages x (A + B) = 110592 B

// Scratch: scores->(in-place) weights; transposed tf32 X; converted row-major X.
__device__ float g_S[(size_t)B_ * T_ * T_];
__device__ float g_Xt[(size_t)B_ * D_ * T_];
__device__ float g_Xc[(size_t)B_ * T_ * D_];

__device__ __forceinline__ uint32_t f2tf32(float v) {
    uint32_t o;
    asm("cvt.rna.tf32.f32 %0, %1;" : "=r"(o) : "f"(v));
    return o;
}

__device__ __forceinline__ void mma_tf32(float& c0, float& c1, float& c2, float& c3,
                                         uint32_t a0, uint32_t a1, uint32_t a2, uint32_t a3,
                                         uint32_t b0, uint32_t b1) {
    asm volatile(
        "mma.sync.aligned.m16n8k8.row.col.f32.tf32.tf32.f32 "
        "{%0,%1,%2,%3}, {%4,%5,%6,%7}, {%8,%9}, {%0,%1,%2,%3};"
        : "+f"(c0), "+f"(c1), "+f"(c2), "+f"(c3)
        : "r"(a0), "r"(a1), "r"(a2), "r"(a3), "r"(b0), "r"(b1));
}

__device__ __forceinline__ void ldsm_x4(uint32_t& r0, uint32_t& r1, uint32_t& r2,
                                        uint32_t& r3, uint32_t addr) {
    asm volatile("ldmatrix.sync.aligned.m8n8.x4.shared.b16 {%0,%1,%2,%3}, [%4];"
                 : "=r"(r0), "=r"(r1), "=r"(r2), "=r"(r3) : "r"(addr));
}

struct Frag { float c[2][8][4]; };

// ---------------------------------------------------------------------------
// cp.async producer: one 128x32 fp32 chunk of each operand into given stage.
// GMEM data is already tf32-rounded, so raw byte copies preserve numerics.
// ---------------------------------------------------------------------------
__device__ __forceinline__ void issue_chunk(const float* __restrict__ A, int lda,
                                            const float* __restrict__ Bp, int ldb,
                                            int k0, uint32_t sA, uint32_t sB) {
    int tid = threadIdx.x;
    int row = tid >> 3, f4 = tid & 7;
#pragma unroll
    for (int p = 0; p < 4; p++) {
        int r = row + p * 32;
        const float* ga = A + (size_t)r * lda + k0 + f4 * 4;
        const float* gb = Bp + (size_t)r * ldb + k0 + f4 * 4;
        uint32_t da = sA + (uint32_t)(r * LDS_ + f4 * 4) * 4u;
        uint32_t db = sB + (uint32_t)(r * LDS_ + f4 * 4) * 4u;
        asm volatile("cp.async.cg.shared.global [%0], [%1], 16;" :: "r"(da), "l"(ga));
        asm volatile("cp.async.cg.shared.global [%0], [%1], 16;" :: "r"(db), "l"(gb));
    }
    asm volatile("cp.async.commit_group;" ::: "memory");
}

// ---------------------------------------------------------------------------
// MMA consumer for one staged chunk — ldmatrix.x4 fragment loads.
// ---------------------------------------------------------------------------
__device__ __forceinline__ void compute_chunk(uint32_t sA, uint32_t sB, Frag& fr) {
    int tid = threadIdx.x, wid = tid >> 5, lane = tid & 31;
    int wr = (wid >> 1) * 32;
    int wc = (wid & 1) * 64;

    uint32_t arow = (uint32_t)(wr + (lane & 7) + ((lane >> 3) & 1) * 8);
    uint32_t akof = (uint32_t)((lane >> 4) & 1) * 4u;
    uint32_t aAddr0 = sA + (arow * LDS_ + akof) * 4u;
    uint32_t aAddr1 = sA + ((arow + 16) * LDS_ + akof) * 4u;

    uint32_t brow = (uint32_t)(wc + ((lane >> 4) & 1) * 8 + (lane & 7));
    uint32_t bkof = (uint32_t)((lane >> 3) & 1) * 4u;
    uint32_t bAddr0 = sB + ((brow + 0) * LDS_ + bkof) * 4u;
    uint32_t bAddr1 = sB + ((brow + 16) * LDS_ + bkof) * 4u;
    uint32_t bAddr2 = sB + ((brow + 32) * LDS_ + bkof) * 4u;
    uint32_t bAddr3 = sB + ((brow + 48) * LDS_ + bkof) * 4u;

#pragma unroll
    for (int ks = 0; ks < 4; ks++) {
        uint32_t kb = (uint32_t)ks * 32u;   // 8 floats = 32 bytes per k-step
        uint32_t a[2][4];
        uint32_t bb[16];
        ldsm_x4(a[0][0], a[0][1], a[0][2], a[0][3], aAddr0 + kb);
        ldsm_x4(a[1][0], a[1][1], a[1][2], a[1][3], aAddr1 + kb);
        ldsm_x4(bb[0],  bb[1],  bb[2],  bb[3],  bAddr0 + kb);
        ldsm_x4(bb[4],  bb[5],  bb[6],  bb[7],  bAddr1 + kb);
        ldsm_x4(bb[8],  bb[9],  bb[10], bb[11], bAddr2 + kb);
        ldsm_x4(bb[12], bb[13], bb[14], bb[15], bAddr3 + kb);
#pragma unroll
        for (int n = 0; n < 8; n++) {
            uint32_t b0 = bb[(n >> 1) * 4 + (n & 1) * 2];
            uint32_t b1 = bb[(n >> 1) * 4 + (n & 1) * 2 + 1];
#pragma unroll
            for (int m = 0; m < 2; m++)
                mma_tf32(fr.c[m][n][0], fr.c[m][n][1], fr.c[m][n][2], fr.c[m][n][3],
                         a[m][0], a[m][1], a[m][2], a[m][3], b0, b1);
        }
    }
}

// ---------------------------------------------------------------------------
// 3-stage pipelined GEMM mainloop, single __syncthreads per chunk.
// ---------------------------------------------------------------------------
__device__ __forceinline__ void run_gemm(const float* __restrict__ A, int lda,
                                         const float* __restrict__ Bp, int ldb,
                                         int nchunks, uint32_t* sm, Frag& fr) {
#pragma unroll
    for (int m = 0; m < 2; m++)
#pragma unroll
        for (int n = 0; n < 8; n++)
#pragma unroll
            for (int q = 0; q < 4; q++) fr.c[m][n][q] = 0.f;

    uint32_t sbase = (uint32_t)__cvta_generic_to_shared(sm);
    uint32_t stA[NSTAGE], stB[NSTAGE];
#pragma unroll
    for (int s = 0; s < NSTAGE; s++) {
        stA[s] = sbase + (uint32_t)(2 * s) * TILE_FLOATS * 4u;
        stB[s] = sbase + (uint32_t)(2 * s + 1) * TILE_FLOATS * 4u;
    }

    issue_chunk(A, lda, Bp, ldb, 0, stA[0], stB[0]);
    if (nchunks > 1) issue_chunk(A, lda, Bp, ldb, KC, stA[1], stB[1]);

    int s = 0;
    for (int c = 0; c < nchunks; c++) {
        if (c + 1 < nchunks)
            asm volatile("cp.async.wait_group 1;" ::: "memory");
        else
            asm volatile("cp.async.wait_group 0;" ::: "memory");
        __syncthreads();
        if (c + 2 < nchunks) {
            int ns = s + 2; if (ns >= NSTAGE) ns -= NSTAGE;
            issue_chunk(A, lda, Bp, ldb, (c + 2) * KC, stA[ns], stB[ns]);
        }
        compute_chunk(stA[s], stB[s], fr);
        if (++s == NSTAGE) s = 0;
    }
}

// ---------------------------------------------------------------------------
// Kernel 1: S[b,i,j] = Xc[b,i,:].Xc[b,j,:] / sqrt(D)  (lower-triangle tiles)
// ---------------------------------------------------------------------------
__global__ void __launch_bounds__(256, 2) qk_mma_kernel() {
    int b = blockIdx.z;
    int i0 = blockIdx.y * 128;
    int j0 = blockIdx.x * 128;
    if (j0 > i0) return;

    extern __shared__ uint32_t sm[];
    const float* A = g_Xc + (size_t)b * T_ * D_ + (size_t)i0 * D_;
    const float* Bp = g_Xc + (size_t)b * T_ * D_ + (size_t)j0 * D_;

    Frag fr;
    run_gemm(A, D_, Bp, D_, D_ / KC, sm, fr);

    int tid = threadIdx.x, wid = tid >> 5, lane = tid & 31;
    int wr = (wid >> 1) * 32, wc = (wid & 1) * 64;
    int g = lane >> 2, tg = lane & 3;
    const float scl = 0.036084391824351615f;  // 1/sqrt(768)
    float* C = g_S + (size_t)b * T_ * T_;
#pragma unroll
    for (int m = 0; m < 2; m++) {
        int r0 = i0 + wr + m * 16 + g;
#pragma unroll
        for (int n = 0; n < 8; n++) {
            int cc = j0 + wc + n * 8 + tg * 2;
            float2 v0 = make_float2(fr.c[m][n][0] * scl, fr.c[m][n][1] * scl);
            float2 v1 = make_float2(fr.c[m][n][2] * scl, fr.c[m][n][3] * scl);
            *(float2*)(C + (size_t)r0 * T_ + cc) = v0;
            *(float2*)(C + (size_t)(r0 + 8) * T_ + cc) = v1;
        }
    }
}

// ---------------------------------------------------------------------------
// Kernel 2: in-place causal softmax + post-softmax sit_mask zeroing.
// Writes only up to the diagonal-tile edge (round_up(i+1,128)) — pv never
// reads beyond it. Weights tf32-rounded so pv can cp.async raw bytes.
// ---------------------------------------------------------------------------
__global__ __launch_bounds__(256) void softmax_kernel(const float* __restrict__ mask) {
    int row = blockIdx.x;
    int b = row >> 11;
    int i = row & (T_ - 1);
    float* srow = g_S + (size_t)b * T_ * T_ + (size_t)i * T_;
    const float* mrow = mask + (size_t)b * T_;
    int tid = threadIdx.x;
    int nend = (i + 128) & ~127;     // round_up(i+1, 128): pv read bound

    __shared__ float sh[T_];
    __shared__ float red[8];

    if (mrow[i] == 0.0f) {
        float4 z = make_float4(0.f, 0.f, 0.f, 0.f);
        for (int j4 = tid; j4 < nend / 4; j4 += 256) ((float4*)srow)[j4] = z;
        return;
    }

    int n = i + 1;
    float lm = -3.4e38f;
    for (int j = tid; j < n; j += 256) { float v = srow[j]; sh[j] = v; lm = fmaxf(lm, v); }
#pragma unroll
    for (int o = 16; o > 0; o >>= 1) lm = fmaxf(lm, __shfl_xor_sync(0xffffffffu, lm, o));
    if ((tid & 31) == 0) red[tid >> 5] = lm;
    __syncthreads();
    float m = red[0];
#pragma unroll
    for (int k = 1; k < 8; k++) m = fmaxf(m, red[k]);
    __syncthreads();

    float ls = 0.f;
    for (int j = tid; j < n; j += 256) ls += __expf(sh[j] - m);
#pragma unroll
    for (int o = 16; o > 0; o >>= 1) ls += __shfl_xor_sync(0xffffffffu, ls, o);
    if ((tid & 31) == 0) red[tid >> 5] = ls;
    __syncthreads();
    float l = red[0];
#pragma unroll
    for (int k = 1; k < 8; k++) l += red[k];
    float inv = 1.0f / l;

    for (int j = tid; j < nend; j += 256) {
        float w = 0.f;
        if (j < n && mrow[j] != 0.f) w = __expf(sh[j] - m) * inv;
        srow[j] = __uint_as_float(f2tf32(w));
    }
}

// ---------------------------------------------------------------------------
// Kernel 2.5: Xt[b,d,j] = tf32(X[b,j,d]); Xc[b,j,d] = tf32(X[b,j,d]);
//             out[b,j,D+d] = X[b,j,d]  (concat half, unconverted)
// ---------------------------------------------------------------------------
__global__ __launch_bounds__(256) void transpose_concat_kernel(const float* __restrict__ X,
                                                               float* __restrict__ out) {
    __shared__ float t[32][33];
    int b = blockIdx.z, j0 = blockIdx.x * 32, d0 = blockIdx.y * 32;
    int tx = threadIdx.x, ty = threadIdx.y;
    const float* Xb = X + (size_t)b * T_ * D_;
    float* Xc = g_Xc + (size_t)b * T_ * D_;
#pragma unroll
    for (int r = 0; r < 32; r += 8) {
        float v = Xb[(size_t)(j0 + ty + r) * D_ + d0 + tx];
        float vt = __uint_as_float(f2tf32(v));
        t[ty + r][tx] = vt;
        out[((size_t)b * T_ + j0 + ty + r) * (2 * D_) + D_ + d0 + tx] = v;
        Xc[(size_t)(j0 + ty + r) * D_ + d0 + tx] = vt;
    }
    __syncthreads();
    float* Xt = g_Xt + (size_t)b * D_ * T_;
#pragma unroll
    for (int r = 0; r < 32; r += 8)
        Xt[(size_t)(d0 + ty + r) * T_ + j0 + tx] = t[tx][ty + r];
}

// ---------------------------------------------------------------------------
// Kernel 3: out[b,i,d] = sum_j W[b,i,j]*Xt[b,d,j]  (K truncated at i0+128).
// i-tiles mapped in DESCENDING K order so long-K CTAs launch first (wave LB).
// ---------------------------------------------------------------------------
__global__ void __launch_bounds__(256, 2) pv_mma_kernel(float* __restrict__ out) {
    int b = blockIdx.z;
    int i0 = (gridDim.y - 1 - blockIdx.y) * 128;   // big K first
    int d0 = blockIdx.x * 128;

    extern __shared__ uint32_t sm[];
    const float* A = g_S + (size_t)b * T_ * T_ + (size_t)i0 * T_;
    const float* Bp = g_Xt + (size_t)b * D_ * T_ + (size_t)d0 * T_;

    Frag fr;
    run_gemm(A, T_, Bp, T_, (i0 + 128) / KC, sm, fr);

    int tid = threadIdx.x, wid = tid >> 5, lane = tid & 31;
    int wr = (wid >> 1) * 32, wc = (wid & 1) * 64;
    int g = lane >> 2, tg = lane & 3;
#pragma unroll
    for (int m = 0; m < 2; m++) {
        int r0 = i0 + wr + m * 16 + g;
#pragma unroll
        for (int n = 0; n < 8; n++) {
            int cc = d0 + wc + n * 8 + tg * 2;
            float2 v0 = make_float2(fr.c[m][n][0], fr.c[m][n][1]);
            float2 v1 = make_float2(fr.c[m][n][2], fr.c[m][n][3]);
            *(float2*)(out + ((size_t)b * T_ + r0) * (2 * D_) + cc) = v0;
            *(float2*)(out + ((size_t)b * T_ + r0 + 8) * (2 * D_) + cc) = v1;
        }
    }
}

extern "C" void kernel_launch(void* const* d_in, const int* in_sizes, int n_in,
                              void* d_out, int out_size) {
    const float* X = (const float*)d_in[0];
    const float* mask = (const float*)d_in[1];
    // d_in[2] (proposition_matrix) is unused by the reference computation.
    float* out = (float*)d_out;

    cudaFuncSetAttribute(qk_mma_kernel, cudaFuncAttributeMaxDynamicSharedMemorySize, SMEM_DYN);
    cudaFuncSetAttribute(pv_mma_kernel, cudaFuncAttributeMaxDynamicSharedMemorySize, SMEM_DYN);

    dim3 gt(T_ / 32, D_ / 32, B_);
    transpose_concat_kernel<<<gt, dim3(32, 8)>>>(X, out);

    dim3 g1(T_ / 128, T_ / 128, B_);
    qk_mma_kernel<<<g1, 256, SMEM_DYN>>>();

    softmax_kernel<<<B_ * T_, 256>>>(mask);

    dim3 g3(D_ / 128, T_ / 128, B_);
    pv_mma_kernel<<<g3, 256, SMEM_DYN>>>(out);
}

// round 11
// speedup vs baseline: 1.4724x; 1.0894x over previous
#include <cuda_runtime.h>
#include <cuda.h>
#include <stdint.h>
#include <math.h>

#define B_ 8
#define T_ 2048
#define D_ 768
#define KC 32
#define LDS_ 36                         // padded row stride (floats)
#define TA_FLOATS (64 * LDS_)           // 2304 floats: A tile (64 rows)
#define TB_FLOATS (128 * LDS_)          // 4608 floats: B tile (128 rows)
#define STAGE_FLOATS (TA_FLOATS + TB_FLOATS)
#define SMEM_DYN (2 * STAGE_FLOATS * 4) // 2 stages = 55296 B

// Scratch: scores->(in-place) weights; transposed tf32 X; converted row-major X.
__device__ float g_S[(size_t)B_ * T_ * T_];
__device__ float g_Xt[(size_t)B_ * D_ * T_];
__device__ float g_Xc[(size_t)B_ * T_ * D_];

__device__ __forceinline__ uint32_t f2tf32(float v) {
    uint32_t o;
    asm("cvt.rna.tf32.f32 %0, %1;" : "=r"(o) : "f"(v));
    return o;
}

__device__ __forceinline__ void mma_tf32(float& c0, float& c1, float& c2, float& c3,
                                         uint32_t a0, uint32_t a1, uint32_t a2, uint32_t a3,
                                         uint32_t b0, uint32_t b1) {
    asm volatile(
        "mma.sync.aligned.m16n8k8.row.col.f32.tf32.tf32.f32 "
        "{%0,%1,%2,%3}, {%4,%5,%6,%7}, {%8,%9}, {%0,%1,%2,%3};"
        : "+f"(c0), "+f"(c1), "+f"(c2), "+f"(c3)
        : "r"(a0), "r"(a1), "r"(a2), "r"(a3), "r"(b0), "r"(b1));
}

__device__ __forceinline__ void ldsm_x4(uint32_t& r0, uint32_t& r1, uint32_t& r2,
                                        uint32_t& r3, uint32_t addr) {
    asm volatile("ldmatrix.sync.aligned.m8n8.x4.shared.b16 {%0,%1,%2,%3}, [%4];"
                 : "=r"(r0), "=r"(r1), "=r"(r2), "=r"(r3) : "r"(addr));
}

struct Frag { float c[2][8][4]; };

// ---------------------------------------------------------------------------
// cp.async producer: A chunk (64x32) + B chunk (128x32) into given stage.
// 128 threads: A 4 float4/thread, B 8 float4/thread.
// ---------------------------------------------------------------------------
__device__ __forceinline__ void issue_chunk(const float* __restrict__ A, int lda,
                                            const float* __restrict__ Bp, int ldb,
                                            int k0, uint32_t sA, uint32_t sB) {
    int tid = threadIdx.x;
    int row = tid >> 3, f4 = tid & 7;
#pragma unroll
    for (int p = 0; p < 4; p++) {
        int r = row + p * 16;
        const float* ga = A + (size_t)r * lda + k0 + f4 * 4;
        uint32_t da = sA + (uint32_t)(r * LDS_ + f4 * 4) * 4u;
        asm volatile("cp.async.cg.shared.global [%0], [%1], 16;" :: "r"(da), "l"(ga));
    }
#pragma unroll
    for (int p = 0; p < 8; p++) {
        int r = row + p * 16;
        const float* gb = Bp + (size_t)r * ldb + k0 + f4 * 4;
        uint32_t db = sB + (uint32_t)(r * LDS_ + f4 * 4) * 4u;
        asm volatile("cp.async.cg.shared.global [%0], [%1], 16;" :: "r"(db), "l"(gb));
    }
    asm volatile("cp.async.commit_group;" ::: "memory");
}

// ---------------------------------------------------------------------------
// MMA consumer: 4 warps in 2x2, warp tile 32x64, ldmatrix.x4 fragment loads.
// ---------------------------------------------------------------------------
__device__ __forceinline__ void compute_chunk(uint32_t sA, uint32_t sB, Frag& fr) {
    int tid = threadIdx.x, wid = tid >> 5, lane = tid & 31;
    int wr = (wid >> 1) * 32;
    int wc = (wid & 1) * 64;

    uint32_t arow = (uint32_t)(wr + (lane & 7) + ((lane >> 3) & 1) * 8);
    uint32_t akof = (uint32_t)((lane >> 4) & 1) * 4u;
    uint32_t aAddr0 = sA + (arow * LDS_ + akof) * 4u;
    uint32_t aAddr1 = sA + ((arow + 16) * LDS_ + akof) * 4u;

    uint32_t brow = (uint32_t)(wc + ((lane >> 4) & 1) * 8 + (lane & 7));
    uint32_t bkof = (uint32_t)((lane >> 3) & 1) * 4u;
    uint32_t bAddr0 = sB + ((brow + 0) * LDS_ + bkof) * 4u;
    uint32_t bAddr1 = sB + ((brow + 16) * LDS_ + bkof) * 4u;
    uint32_t bAddr2 = sB + ((brow + 32) * LDS_ + bkof) * 4u;
    uint32_t bAddr3 = sB + ((brow + 48) * LDS_ + bkof) * 4u;

#pragma unroll
    for (int ks = 0; ks < 4; ks++) {
        uint32_t kb = (uint32_t)ks * 32u;   // 8 floats = 32 bytes per k-step
        uint32_t a[2][4];
        uint32_t bb[16];
        ldsm_x4(a[0][0], a[0][1], a[0][2], a[0][3], aAddr0 + kb);
        ldsm_x4(a[1][0], a[1][1], a[1][2], a[1][3], aAddr1 + kb);
        ldsm_x4(bb[0],  bb[1],  bb[2],  bb[3],  bAddr0 + kb);
        ldsm_x4(bb[4],  bb[5],  bb[6],  bb[7],  bAddr1 + kb);
        ldsm_x4(bb[8],  bb[9],  bb[10], bb[11], bAddr2 + kb);
        ldsm_x4(bb[12], bb[13], bb[14], bb[15], bAddr3 + kb);
#pragma unroll
        for (int n = 0; n < 8; n++) {
            uint32_t b0 = bb[(n >> 1) * 4 + (n & 1) * 2];
            uint32_t b1 = bb[(n >> 1) * 4 + (n & 1) * 2 + 1];
#pragma unroll
            for (int m = 0; m < 2; m++)
                mma_tf32(fr.c[m][n][0], fr.c[m][n][1], fr.c[m][n][2], fr.c[m][n][3],
                         a[m][0], a[m][1], a[m][2], a[m][3], b0, b1);
        }
    }
}

// ---------------------------------------------------------------------------
// Double-buffered GEMM mainloop: C(64x128) += A(64xK) * B(128xK)^T.
// ---------------------------------------------------------------------------
__device__ __forceinline__ void run_gemm(const float* __restrict__ A, int lda,
                                         const float* __restrict__ Bp, int ldb,
                                         int nchunks, uint32_t* sm, Frag& fr) {
#pragma unroll
    for (int m = 0; m < 2; m++)
#pragma unroll
        for (int n = 0; n < 8; n++)
#pragma unroll
            for (int q = 0; q < 4; q++) fr.c[m][n][q] = 0.f;

    uint32_t sbase = (uint32_t)__cvta_generic_to_shared(sm);
    uint32_t stA[2] = { sbase, sbase + STAGE_FLOATS * 4u };
    uint32_t stB[2] = { sbase + TA_FLOATS * 4u, sbase + (STAGE_FLOATS + TA_FLOATS) * 4u };

    issue_chunk(A, lda, Bp, ldb, 0, stA[0], stB[0]);
    for (int c = 0; c < nchunks; c++) {
        if (c + 1 < nchunks) {
            issue_chunk(A, lda, Bp, ldb, (c + 1) * KC, stA[(c + 1) & 1], stB[(c + 1) & 1]);
            asm volatile("cp.async.wait_group 1;" ::: "memory");
        } else {
            asm volatile("cp.async.wait_group 0;" ::: "memory");
        }
        __syncthreads();
        compute_chunk(stA[c & 1], stB[c & 1], fr);
        __syncthreads();
    }
}

// ---------------------------------------------------------------------------
// Kernel 1: S[b,i,j] = Xc[b,i,:].Xc[b,j,:] / sqrt(D)  (tiles with j0 <= i0+63)
// ---------------------------------------------------------------------------
__global__ void __launch_bounds__(128, 4) qk_mma_kernel() {
    int b = blockIdx.z;
    int i0 = blockIdx.y * 64;
    int j0 = blockIdx.x * 128;
    if (j0 > i0) return;   // tile entirely above diagonal

    extern __shared__ uint32_t sm[];
    const float* A = g_Xc + (size_t)b * T_ * D_ + (size_t)i0 * D_;
    const float* Bp = g_Xc + (size_t)b * T_ * D_ + (size_t)j0 * D_;

    Frag fr;
    run_gemm(A, D_, Bp, D_, D_ / KC, sm, fr);

    int tid = threadIdx.x, wid = tid >> 5, lane = tid & 31;
    int wr = (wid >> 1) * 32, wc = (wid & 1) * 64;
    int g = lane >> 2, tg = lane & 3;
    const float scl = 0.036084391824351615f;  // 1/sqrt(768)
    float* C = g_S + (size_t)b * T_ * T_;
#pragma unroll
    for (int m = 0; m < 2; m++) {
        int r0 = i0 + wr + m * 16 + g;
#pragma unroll
        for (int n = 0; n < 8; n++) {
            int cc = j0 + wc + n * 8 + tg * 2;
            float2 v0 = make_float2(fr.c[m][n][0] * scl, fr.c[m][n][1] * scl);
            float2 v1 = make_float2(fr.c[m][n][2] * scl, fr.c[m][n][3] * scl);
            *(float2*)(C + (size_t)r0 * T_ + cc) = v0;
            *(float2*)(C + (size_t)(r0 + 8) * T_ + cc) = v1;
        }
    }
}

// ---------------------------------------------------------------------------
// Kernel 2: in-place causal softmax + post-softmax sit_mask zeroing.
// Writes only up to round_up(i+1,128) — pv never reads beyond it.
// ---------------------------------------------------------------------------
__global__ __launch_bounds__(256) void softmax_kernel(const float* __restrict__ mask) {
    int row = blockIdx.x;
    int b = row >> 11;
    int i = row & (T_ - 1);
    float* srow = g_S + (size_t)b * T_ * T_ + (size_t)i * T_;
    const float* mrow = mask + (size_t)b * T_;
    int tid = threadIdx.x;
    int nend = (i + 128) & ~127;     // round_up(i+1, 128): pv read bound

    __shared__ float sh[T_];
    __shared__ float red[8];

    if (mrow[i] == 0.0f) {
        float4 z = make_float4(0.f, 0.f, 0.f, 0.f);
        for (int j4 = tid; j4 < nend / 4; j4 += 256) ((float4*)srow)[j4] = z;
        return;
    }

    int n = i + 1;
    float lm = -3.4e38f;
    for (int j = tid; j < n; j += 256) { float v = srow[j]; sh[j] = v; lm = fmaxf(lm, v); }
#pragma unroll
    for (int o = 16; o > 0; o >>= 1) lm = fmaxf(lm, __shfl_xor_sync(0xffffffffu, lm, o));
    if ((tid & 31) == 0) red[tid >> 5] = lm;
    __syncthreads();
    float m = red[0];
#pragma unroll
    for (int k = 1; k < 8; k++) m = fmaxf(m, red[k]);
    __syncthreads();

    float ls = 0.f;
    for (int j = tid; j < n; j += 256) ls += __expf(sh[j] - m);
#pragma unroll
    for (int o = 16; o > 0; o >>= 1) ls += __shfl_xor_sync(0xffffffffu, ls, o);
    if ((tid & 31) == 0) red[tid >> 5] = ls;
    __syncthreads();
    float l = red[0];
#pragma unroll
    for (int k = 1; k < 8; k++) l += red[k];
    float inv = 1.0f / l;

    for (int j = tid; j < nend; j += 256) {
        float w = 0.f;
        if (j < n && mrow[j] != 0.f) w = __expf(sh[j] - m) * inv;
        srow[j] = __uint_as_float(f2tf32(w));
    }
}

// ---------------------------------------------------------------------------
// Kernel 2.5: Xt[b,d,j] = tf32(X[b,j,d]); Xc[b,j,d] = tf32(X[b,j,d]);
//             out[b,j,D+d] = X[b,j,d]  (concat half, unconverted)
// ---------------------------------------------------------------------------
__global__ __launch_bounds__(256) void transpose_concat_kernel(const float* __restrict__ X,
                                                               float* __restrict__ out) {
    __shared__ float t[32][33];
    int b = blockIdx.z, j0 = blockIdx.x * 32, d0 = blockIdx.y * 32;
    int tx = threadIdx.x, ty = threadIdx.y;
    const float* Xb = X + (size_t)b * T_ * D_;
    float* Xc = g_Xc + (size_t)b * T_ * D_;
#pragma unroll
    for (int r = 0; r < 32; r += 8) {
        float v = Xb[(size_t)(j0 + ty + r) * D_ + d0 + tx];
        float vt = __uint_as_float(f2tf32(v));
        t[ty + r][tx] = vt;
        out[((size_t)b * T_ + j0 + ty + r) * (2 * D_) + D_ + d0 + tx] = v;
        Xc[(size_t)(j0 + ty + r) * D_ + d0 + tx] = vt;
    }
    __syncthreads();
    float* Xt = g_Xt + (size_t)b * D_ * T_;
#pragma unroll
    for (int r = 0; r < 32; r += 8)
        Xt[(size_t)(d0 + ty + r) * T_ + j0 + tx] = t[tx][ty + r];
}

// ---------------------------------------------------------------------------
// Kernel 3: out[b,i,d] = sum_j W[b,i,j]*Xt[b,d,j]  (K truncated at i0+64,
// rounded up to 128). i-tiles mapped DESCENDING-K (wave LB).
// ---------------------------------------------------------------------------
__global__ void __launch_bounds__(128, 4) pv_mma_kernel(float* __restrict__ out) {
    int b = blockIdx.z;
    int i0 = (gridDim.y - 1 - blockIdx.y) * 64;    // big K first
    int d0 = blockIdx.x * 128;

    extern __shared__ uint32_t sm[];
    const float* A = g_S + (size_t)b * T_ * T_ + (size_t)i0 * T_;
    const float* Bp = g_Xt + (size_t)b * D_ * T_ + (size_t)d0 * T_;

    int kend = (i0 + 128) & ~127;   // W rows valid to 128-boundary (softmax zero-fills)
    Frag fr;
    run_gemm(A, T_, Bp, T_, kend / KC, sm, fr);

    int tid = threadIdx.x, wid = tid >> 5, lane = tid & 31;
    int wr = (wid >> 1) * 32, wc = (wid & 1) * 64;
    int g = lane >> 2, tg = lane & 3;
#pragma unroll
    for (int m = 0; m < 2; m++) {
        int r0 = i0 + wr + m * 16 + g;
#pragma unroll
        for (int n = 0; n < 8; n++) {
            int cc = d0 + wc + n * 8 + tg * 2;
            float2 v0 = make_float2(fr.c[m][n][0], fr.c[m][n][1]);
            float2 v1 = make_float2(fr.c[m][n][2], fr.c[m][n][3]);
            *(float2*)(out + ((size_t)b * T_ + r0) * (2 * D_) + cc) = v0;
            *(float2*)(out + ((size_t)b * T_ + r0 + 8) * (2 * D_) + cc) = v1;
        }
    }
}

extern "C" void kernel_launch(void* const* d_in, const int* in_sizes, int n_in,
                              void* d_out, int out_size) {
    const float* X = (const float*)d_in[0];
    const float* mask = (const float*)d_in[1];
    // d_in[2] (proposition_matrix) is unused by the reference computation.
    float* out = (float*)d_out;

    cudaFuncSetAttribute(qk_mma_kernel, cudaFuncAttributeMaxDynamicSharedMemorySize, SMEM_DYN);
    cudaFuncSetAttribute(pv_mma_kernel, cudaFuncAttributeMaxDynamicSharedMemorySize, SMEM_DYN);

    dim3 gt(T_ / 32, D_ / 32, B_);
    transpose_concat_kernel<<<gt, dim3(32, 8)>>>(X, out);

    dim3 g1(T_ / 128, T_ / 64, B_);
    qk_mma_kernel<<<g1, 128, SMEM_DYN>>>();

    softmax_kernel<<<B_ * T_, 256>>>(mask);

    dim3 g3(D_ / 128, T_ / 64, B_);
    pv_mma_kernel<<<g3, 128, SMEM_DYN>>>(out);
}

// round 12
// speedup vs baseline: 1.5091x; 1.0249x over previous
#include <cuda_runtime.h>
#include <cuda.h>
#include <stdint.h>
#include <math.h>

#define B_ 8
#define T_ 2048
#define D_ 768
#define KC 32
#define LDS_ 36                         // padded row stride (floats)
#define TA_FLOATS (64 * LDS_)           // 2304 floats: A tile (64 rows)
#define TB_FLOATS (128 * LDS_)          // 4608 floats: B tile (128 rows)
#define STAGE_FLOATS (TA_FLOATS + TB_FLOATS)
#define SMEM_DYN (2 * STAGE_FLOATS * 4) // 2 stages = 55296 B

// Scratch: scores->(in-place) weights; transposed tf32 X; converted row-major X.
__device__ float g_S[(size_t)B_ * T_ * T_];
__device__ float g_Xt[(size_t)B_ * D_ * T_];
__device__ float g_Xc[(size_t)B_ * T_ * D_];

__device__ __forceinline__ uint32_t f2tf32(float v) {
    uint32_t o;
    asm("cvt.rna.tf32.f32 %0, %1;" : "=r"(o) : "f"(v));
    return o;
}

__device__ __forceinline__ void mma_tf32(float& c0, float& c1, float& c2, float& c3,
                                         uint32_t a0, uint32_t a1, uint32_t a2, uint32_t a3,
                                         uint32_t b0, uint32_t b1) {
    asm volatile(
        "mma.sync.aligned.m16n8k8.row.col.f32.tf32.tf32.f32 "
        "{%0,%1,%2,%3}, {%4,%5,%6,%7}, {%8,%9}, {%0,%1,%2,%3};"
        : "+f"(c0), "+f"(c1), "+f"(c2), "+f"(c3)
        : "r"(a0), "r"(a1), "r"(a2), "r"(a3), "r"(b0), "r"(b1));
}

__device__ __forceinline__ void ldsm_x4(uint32_t& r0, uint32_t& r1, uint32_t& r2,
                                        uint32_t& r3, uint32_t addr) {
    asm volatile("ldmatrix.sync.aligned.m8n8.x4.shared.b16 {%0,%1,%2,%3}, [%4];"
                 : "=r"(r0), "=r"(r1), "=r"(r2), "=r"(r3) : "r"(addr));
}

struct Frag { float c[2][8][4]; };
struct FragAddr { uint32_t a0, a1, b0, b1, b2, b3; };  // byte offsets into stage

__device__ __forceinline__ FragAddr make_addr() {
    int tid = threadIdx.x, wid = tid >> 5, lane = tid & 31;
    int wr = (wid >> 1) * 32;
    int wc = (wid & 1) * 64;
    FragAddr fa;
    uint32_t arow = (uint32_t)(wr + (lane & 7) + ((lane >> 3) & 1) * 8);
    uint32_t akof = (uint32_t)((lane >> 4) & 1) * 4u;
    fa.a0 = (arow * LDS_ + akof) * 4u;
    fa.a1 = ((arow + 16) * LDS_ + akof) * 4u;
    uint32_t brow = (uint32_t)(wc + ((lane >> 4) & 1) * 8 + (lane & 7));
    uint32_t bkof = (uint32_t)((lane >> 3) & 1) * 4u;
    fa.b0 = ((brow + 0) * LDS_ + bkof) * 4u;
    fa.b1 = ((brow + 16) * LDS_ + bkof) * 4u;
    fa.b2 = ((brow + 32) * LDS_ + bkof) * 4u;
    fa.b3 = ((brow + 48) * LDS_ + bkof) * 4u;
    return fa;
}

// One k-step (8 floats of K): 6 LDSM + 16 MMA.
__device__ __forceinline__ void compute_ks(uint32_t sA, uint32_t sB, const FragAddr& fa,
                                           int ksIdx, Frag& fr) {
    uint32_t kb = (uint32_t)ksIdx * 32u;
    uint32_t a[2][4];
    uint32_t bb[16];
    ldsm_x4(a[0][0], a[0][1], a[0][2], a[0][3], sA + fa.a0 + kb);
    ldsm_x4(a[1][0], a[1][1], a[1][2], a[1][3], sA + fa.a1 + kb);
    ldsm_x4(bb[0],  bb[1],  bb[2],  bb[3],  sB + fa.b0 + kb);
    ldsm_x4(bb[4],  bb[5],  bb[6],  bb[7],  sB + fa.b1 + kb);
    ldsm_x4(bb[8],  bb[9],  bb[10], bb[11], sB + fa.b2 + kb);
    ldsm_x4(bb[12], bb[13], bb[14], bb[15], sB + fa.b3 + kb);
#pragma unroll
    for (int n = 0; n < 8; n++) {
        uint32_t b0 = bb[(n >> 1) * 4 + (n & 1) * 2];
        uint32_t b1 = bb[(n >> 1) * 4 + (n & 1) * 2 + 1];
#pragma unroll
        for (int m = 0; m < 2; m++)
            mma_tf32(fr.c[m][n][0], fr.c[m][n][1], fr.c[m][n][2], fr.c[m][n][3],
                     a[m][0], a[m][1], a[m][2], a[m][3], b0, b1);
    }
}

// ---------------------------------------------------------------------------
// cp.async producer: A chunk (64x32) + B chunk (128x32) into given stage.
// ---------------------------------------------------------------------------
__device__ __forceinline__ void issue_chunk(const float* __restrict__ A, int lda,
                                            const float* __restrict__ Bp, int ldb,
                                            int k0, uint32_t sA, uint32_t sB) {
    int tid = threadIdx.x;
    int row = tid >> 3, f4 = tid & 7;
#pragma unroll
    for (int p = 0; p < 4; p++) {
        int r = row + p * 16;
        const float* ga = A + (size_t)r * lda + k0 + f4 * 4;
        uint32_t da = sA + (uint32_t)(r * LDS_ + f4 * 4) * 4u;
        asm volatile("cp.async.cg.shared.global [%0], [%1], 16;" :: "r"(da), "l"(ga));
    }
#pragma unroll
    for (int p = 0; p < 8; p++) {
        int r = row + p * 16;
        const float* gb = Bp + (size_t)r * ldb + k0 + f4 * 4;
        uint32_t db = sB + (uint32_t)(r * LDS_ + f4 * 4) * 4u;
        asm volatile("cp.async.cg.shared.global [%0], [%1], 16;" :: "r"(db), "l"(gb));
    }
    asm volatile("cp.async.commit_group;" ::: "memory");
}

// ---------------------------------------------------------------------------
// 2-stage mainloop: single barrier per chunk, warp-staggered ks order,
// producer issued mid-chunk (after the first ks block).
// Stage (c&1) is overwritten only in iter c+1 AFTER its top barrier, which all
// warps reach only after finishing iter c's reads -> one bar/chunk is safe.
// ---------------------------------------------------------------------------
__device__ __forceinline__ void run_gemm(const float* __restrict__ A, int lda,
                                         const float* __restrict__ Bp, int ldb,
                                         int nchunks, uint32_t* sm, Frag& fr) {
#pragma unroll
    for (int m = 0; m < 2; m++)
#pragma unroll
        for (int n = 0; n < 8; n++)
#pragma unroll
            for (int q = 0; q < 4; q++) fr.c[m][n][q] = 0.f;

    uint32_t sbase = (uint32_t)__cvta_generic_to_shared(sm);
    uint32_t stA[2] = { sbase, sbase + STAGE_FLOATS * 4u };
    uint32_t stB[2] = { sbase + TA_FLOATS * 4u, sbase + (STAGE_FLOATS + TA_FLOATS) * 4u };

    FragAddr fa = make_addr();
    int ks0 = (threadIdx.x >> 5) & 3;   // warp-staggered start k-step

    issue_chunk(A, lda, Bp, ldb, 0, stA[0], stB[0]);
    for (int c = 0; c < nchunks; c++) {
        asm volatile("cp.async.wait_group 0;" ::: "memory");
        __syncthreads();
        uint32_t sA = stA[c & 1], sB = stB[c & 1];
        compute_ks(sA, sB, fa, ks0, fr);
        if (c + 1 < nchunks)
            issue_chunk(A, lda, Bp, ldb, (c + 1) * KC, stA[(c + 1) & 1], stB[(c + 1) & 1]);
#pragma unroll
        for (int t = 1; t < 4; t++)
            compute_ks(sA, sB, fa, (ks0 + t) & 3, fr);
    }
}

// ---------------------------------------------------------------------------
// Kernel 1: S[b,i,j] = Xc[b,i,:].Xc[b,j,:] / sqrt(D)  (tiles with j0 <= i0)
// ---------------------------------------------------------------------------
__global__ void __launch_bounds__(128, 4) qk_mma_kernel() {
    int b = blockIdx.z;
    int i0 = blockIdx.y * 64;
    int j0 = blockIdx.x * 128;
    if (j0 > i0) return;   // tile entirely above diagonal

    extern __shared__ uint32_t sm[];
    const float* A = g_Xc + (size_t)b * T_ * D_ + (size_t)i0 * D_;
    const float* Bp = g_Xc + (size_t)b * T_ * D_ + (size_t)j0 * D_;

    Frag fr;
    run_gemm(A, D_, Bp, D_, D_ / KC, sm, fr);

    int tid = threadIdx.x, wid = tid >> 5, lane = tid & 31;
    int wr = (wid >> 1) * 32, wc = (wid & 1) * 64;
    int g = lane >> 2, tg = lane & 3;
    const float scl = 0.036084391824351615f;  // 1/sqrt(768)
    float* C = g_S + (size_t)b * T_ * T_;
#pragma unroll
    for (int m = 0; m < 2; m++) {
        int r0 = i0 + wr + m * 16 + g;
#pragma unroll
        for (int n = 0; n < 8; n++) {
            int cc = j0 + wc + n * 8 + tg * 2;
            float2 v0 = make_float2(fr.c[m][n][0] * scl, fr.c[m][n][1] * scl);
            float2 v1 = make_float2(fr.c[m][n][2] * scl, fr.c[m][n][3] * scl);
            *(float2*)(C + (size_t)r0 * T_ + cc) = v0;
            *(float2*)(C + (size_t)(r0 + 8) * T_ + cc) = v1;
        }
    }
}

// ---------------------------------------------------------------------------
// Kernel 2: in-place causal softmax + post-softmax sit_mask zeroing.
// Writes only up to round_up(i+1,128) — pv never reads beyond it.
// ---------------------------------------------------------------------------
__global__ __launch_bounds__(256) void softmax_kernel(const float* __restrict__ mask) {
    int row = blockIdx.x;
    int b = row >> 11;
    int i = row & (T_ - 1);
    float* srow = g_S + (size_t)b * T_ * T_ + (size_t)i * T_;
    const float* mrow = mask + (size_t)b * T_;
    int tid = threadIdx.x;
    int nend = (i + 128) & ~127;     // round_up(i+1, 128): pv read bound

    __shared__ float sh[T_];
    __shared__ float red[8];

    if (mrow[i] == 0.0f) {
        float4 z = make_float4(0.f, 0.f, 0.f, 0.f);
        for (int j4 = tid; j4 < nend / 4; j4 += 256) ((float4*)srow)[j4] = z;
        return;
    }

    int n = i + 1;
    float lm = -3.4e38f;
    for (int j = tid; j < n; j += 256) { float v = srow[j]; sh[j] = v; lm = fmaxf(lm, v); }
#pragma unroll
    for (int o = 16; o > 0; o >>= 1) lm = fmaxf(lm, __shfl_xor_sync(0xffffffffu, lm, o));
    if ((tid & 31) == 0) red[tid >> 5] = lm;
    __syncthreads();
    float m = red[0];
#pragma unroll
    for (int k = 1; k < 8; k++) m = fmaxf(m, red[k]);
    __syncthreads();

    float ls = 0.f;
    for (int j = tid; j < n; j += 256) ls += __expf(sh[j] - m);
#pragma unroll
    for (int o = 16; o > 0; o >>= 1) ls += __shfl_xor_sync(0xffffffffu, ls, o);
    if ((tid & 31) == 0) red[tid >> 5] = ls;
    __syncthreads();
    float l = red[0];
#pragma unroll
    for (int k = 1; k < 8; k++) l += red[k];
    float inv = 1.0f / l;

    for (int j = tid; j < nend; j += 256) {
        float w = 0.f;
        if (j < n && mrow[j] != 0.f) w = __expf(sh[j] - m) * inv;
        srow[j] = __uint_as_float(f2tf32(w));
    }
}

// ---------------------------------------------------------------------------
// Kernel 2.5: Xt[b,d,j] = tf32(X[b,j,d]); Xc[b,j,d] = tf32(X[b,j,d]);
//             out[b,j,D+d] = X[b,j,d]  (concat half, unconverted)
// ---------------------------------------------------------------------------
__global__ __launch_bounds__(256) void transpose_concat_kernel(const float* __restrict__ X,
                                                               float* __restrict__ out) {
    __shared__ float t[32][33];
    int b = blockIdx.z, j0 = blockIdx.x * 32, d0 = blockIdx.y * 32;
    int tx = threadIdx.x, ty = threadIdx.y;
    const float* Xb = X + (size_t)b * T_ * D_;
    float* Xc = g_Xc + (size_t)b * T_ * D_;
#pragma unroll
    for (int r = 0; r < 32; r += 8) {
        float v = Xb[(size_t)(j0 + ty + r) * D_ + d0 + tx];
        float vt = __uint_as_float(f2tf32(v));
        t[ty + r][tx] = vt;
        out[((size_t)b * T_ + j0 + ty + r) * (2 * D_) + D_ + d0 + tx] = v;
        Xc[(size_t)(j0 + ty + r) * D_ + d0 + tx] = vt;
    }
    __syncthreads();
    float* Xt = g_Xt + (size_t)b * D_ * T_;
#pragma unroll
    for (int r = 0; r < 32; r += 8)
        Xt[(size_t)(d0 + ty + r) * T_ + j0 + tx] = t[tx][ty + r];
}

// ---------------------------------------------------------------------------
// Kernel 3: out[b,i,d] = sum_j W[b,i,j]*Xt[b,d,j]  (K truncated at i0+64,
// rounded up to 128). i-tiles mapped DESCENDING-K (wave LB).
// ---------------------------------------------------------------------------
__global__ void __launch_bounds__(128, 4) pv_mma_kernel(float* __restrict__ out) {
    int b = blockIdx.z;
    int i0 = (gridDim.y - 1 - blockIdx.y) * 64;    // big K first
    int d0 = blockIdx.x * 128;

    extern __shared__ uint32_t sm[];
    const float* A = g_S + (size_t)b * T_ * T_ + (size_t)i0 * T_;
    const float* Bp = g_Xt + (size_t)b * D_ * T_ + (size_t)d0 * T_;

    int kend = (i0 + 128) & ~127;   // W rows valid to 128-boundary (softmax zero-fills)
    Frag fr;
    run_gemm(A, T_, Bp, T_, kend / KC, sm, fr);

    int tid = threadIdx.x, wid = tid >> 5, lane = tid & 31;
    int wr = (wid >> 1) * 32, wc = (wid & 1) * 64;
    int g = lane >> 2, tg = lane & 3;
#pragma unroll
    for (int m = 0; m < 2; m++) {
        int r0 = i0 + wr + m * 16 + g;
#pragma unroll
        for (int n = 0; n < 8; n++) {
            int cc = d0 + wc + n * 8 + tg * 2;
            float2 v0 = make_float2(fr.c[m][n][0], fr.c[m][n][1]);
            float2 v1 = make_float2(fr.c[m][n][2], fr.c[m][n][3]);
            *(float2*)(out + ((size_t)b * T_ + r0) * (2 * D_) + cc) = v0;
            *(float2*)(out + ((size_t)b * T_ + r0 + 8) * (2 * D_) + cc) = v1;
        }
    }
}

extern "C" void kernel_launch(void* const* d_in, const int* in_sizes, int n_in,
                              void* d_out, int out_size) {
    const float* X = (const float*)d_in[0];
    const float* mask = (const float*)d_in[1];
    // d_in[2] (proposition_matrix) is unused by the reference computation.
    float* out = (float*)d_out;

    cudaFuncSetAttribute(qk_mma_kernel, cudaFuncAttributeMaxDynamicSharedMemorySize, SMEM_DYN);
    cudaFuncSetAttribute(pv_mma_kernel, cudaFuncAttributeMaxDynamicSharedMemorySize, SMEM_DYN);

    dim3 gt(T_ / 32, D_ / 32, B_);
    transpose_concat_kernel<<<gt, dim3(32, 8)>>>(X, out);

    dim3 g1(T_ / 128, T_ / 64, B_);
    qk_mma_kernel<<<g1, 128, SMEM_DYN>>>();

    softmax_kernel<<<B_ * T_, 256>>>(mask);

    dim3 g3(D_ / 128, T_ / 64, B_);
    pv_mma_kernel<<<g3, 128, SMEM_DYN>>>(out);
}